// round 16
// baseline (speedup 1.0000x reference)
#include <cuda_runtime.h>
#include <cuda_bf16.h>
#include <cstdint>

// Problem constants (shape fixed by dataset: img [64, 3, 512, 512])
constexpr int NCH = 192;           // 64*3 channels
constexpr int P   = 262144;        // 512*512 pixels / channel
constexpr int NB  = 256;           // bins

// Pipeline structure: R13 topology with 2x finer group granularity.
// Same 576 blocks, same per-block work; half-size groups halve pipeline fill
// and halve the hist->apply temporal lag (input window ~25MB stays L2-hot).
constexpr int GROUPS = 16;
constexpr int CPG    = NCH / GROUPS;   // 12 channels per group
constexpr int HPC    = 16;             // hist blocks per channel
constexpr int APC    = 32;             // apply blocks per channel
constexpr int NHIST  = CPG * HPC;      // 192
constexpr int NAPPLY = CPG * APC;      // 384
constexpr int NBLK   = NHIST + NAPPLY; // 576 <= 148*4 -> fully co-resident

// Scratch — __device__ globals.
// g_part: per-slice partial histograms, PLAIN STORES, fully overwritten every
//         run -> no cross-replay zeroing needed (validated neutral in R13).
// g_ctr:  hist-done per group; reset by the tiny trailing kernel.
__device__ int g_part[NCH * HPC * NB];   // 3.1 MB, L2-resident during handoff
__device__ int g_ctr [GROUPS];

// ---------------------------------------------------------------------------
// Fused persistent kernel (R13 structure, constants refined only):
//  - 192 hist blocks (read-bound): per-warp smem hists -> plain-store partial
//    per (channel, slice), bump group counter.
//  - 384 apply blocks (write-bound): spin on group counter, build LUT locally
//    from the 16 partials (exact PIL math), translate + __stcs-write slice.
// ---------------------------------------------------------------------------
__global__ void __launch_bounds__(256, 4) fused_kernel(const float* __restrict__ in,
                                                       float* __restrict__ out) {
    __shared__ int sh[8 * NB];     // hist: 8 per-warp hists. apply: H/CS/RED/LUT.
    const int tid = threadIdx.x;
    const int bid = blockIdx.x;

    if (bid < NHIST) {
        // ---------------- HIST ROLE (R13 code, new constants) ----------------
        const int cg = bid / HPC;          // channel within group
        const int h  = bid % HPC;          // slice within channel
        int* const myh = &sh[(tid >> 5) * NB];

        for (int g = 0; g < GROUPS; g++) {
            const int c = g * CPG + cg;
            for (int i = tid; i < 8 * NB; i += 256) sh[i] = 0;
            __syncthreads();

            const float4* bi =
                reinterpret_cast<const float4*>(in + (size_t)c * P) + h * (P / 4 / HPC);
            for (int i = tid; i < P / 4 / HPC; i += 512) {   // 4096 float4 / slice
                float4 a = bi[i];
                float4 b = bi[i + 256];
                atomicAdd(&myh[(int)a.x], 1);
                atomicAdd(&myh[(int)a.y], 1);
                atomicAdd(&myh[(int)a.z], 1);
                atomicAdd(&myh[(int)a.w], 1);
                atomicAdd(&myh[(int)b.x], 1);
                atomicAdd(&myh[(int)b.y], 1);
                atomicAdd(&myh[(int)b.z], 1);
                atomicAdd(&myh[(int)b.w], 1);
            }
            __syncthreads();

            // Reduce 8 warp-hists -> plain store of this slice's partial.
            int s = 0;
#pragma unroll
            for (int k = 0; k < 8; k++) s += sh[k * NB + tid];
            g_part[(c * HPC + h) * NB + tid] = s;

            __threadfence();               // release my partial before counting
            __syncthreads();               // all threads' stores+fences done
            if (tid == 0) atomicAdd(&g_ctr[g], 1);
        }
    } else {
        // ---------------- APPLY ROLE (R13 code, new constants) ---------------
        const int a  = bid - NHIST;
        const int cg = a / APC;            // channel within group
        const int j  = a % APC;            // slice within channel
        int*   H   = sh;
        int*   CS  = sh + NB;
        int*   RED = sh + 2 * NB;
        float* LUT = reinterpret_cast<float*>(sh + 3 * NB);

        for (int g = 0; g < GROUPS; g++) {
            const int c = g * CPG + cg;

            // Wait until all hist blocks of this group have published.
            if (tid == 0) {
                while (*(volatile int*)&g_ctr[g] < NHIST) __nanosleep(128);
            }
            __syncthreads();
            __threadfence();

            // Build this channel's LUT locally (exact PIL integer math).
            int hv = 0;
#pragma unroll
            for (int k = 0; k < HPC; k++)
                hv += __ldcg(&g_part[(c * HPC + k) * NB + tid]);
            H[tid]  = hv;
            CS[tid] = hv;
            __syncthreads();
#pragma unroll
            for (int off = 1; off < NB; off <<= 1) {       // inclusive scan
                int v = (tid >= off) ? CS[tid - off] : 0;
                __syncthreads();
                CS[tid] += v;
                __syncthreads();
            }
            RED[tid] = hv ? tid : -1;                      // last nonzero bin
            __syncthreads();
#pragma unroll
            for (int sdx = 128; sdx > 0; sdx >>= 1) {
                if (tid < sdx) RED[tid] = max(RED[tid], RED[tid + sdx]);
                __syncthreads();
            }
            const int last_val = H[RED[0]];
            const int step = (P - last_val) / 255;
            const int safe = step > 0 ? step : 1;
            const int prev = tid ? CS[tid - 1] : 0;
            int lv = (prev + step / 2) / safe;
            lv = min(max(lv, 0), 255);
            if (step == 0) lv = tid;       // passthrough as identity LUT
            LUT[tid] = (float)lv;
            __syncthreads();

            // Apply this block's slice: 2048 float4, 2 loads in flight.
            // Freshly-histogrammed input (half-size groups) -> L2 hits likely.
            const float4* bi =
                reinterpret_cast<const float4*>(in + (size_t)c * P) + j * (P / 4 / APC);
            float4* bo =
                reinterpret_cast<float4*>(out + (size_t)c * P) + j * (P / 4 / APC);
            for (int i = tid; i < P / 4 / APC; i += 512) {
                float4 x = bi[i];
                float4 y = bi[i + 256];
                float4 ox, oy;
                ox.x = LUT[(int)x.x]; ox.y = LUT[(int)x.y];
                ox.z = LUT[(int)x.z]; ox.w = LUT[(int)x.w];
                oy.x = LUT[(int)y.x]; oy.y = LUT[(int)y.y];
                oy.z = LUT[(int)y.z]; oy.w = LUT[(int)y.w];
                __stcs(&bo[i], ox);            // evict-first writes: protect L2
                __stcs(&bo[i + 256], oy);      // residency of upcoming input
            }
            __syncthreads();                    // smem reuse next group
        }
    }
}

// ---------------------------------------------------------------------------
// Tiny cleanup: reset the 16 group counters so the next graph replay starts
// clean. (Partial histograms need no reset — plain-store overwritten.)
// ---------------------------------------------------------------------------
__global__ void cleanup_kernel() {
    if (threadIdx.x < GROUPS) g_ctr[threadIdx.x] = 0;
}

// ---------------------------------------------------------------------------
extern "C" void kernel_launch(void* const* d_in, const int* in_sizes, int n_in,
                              void* d_out, int out_size) {
    const float* img = (const float*)d_in[0];
    float* out = (float*)d_out;

    fused_kernel<<<NBLK, 256>>>(img, out);
    cleanup_kernel<<<1, 32>>>();
}

// round 17
// speedup vs baseline: 1.3978x; 1.3978x over previous
#include <cuda_runtime.h>
#include <cuda_bf16.h>
#include <cstdint>

// Problem constants (shape fixed by dataset: img [64, 3, 512, 512])
constexpr int NCH = 192;           // 64*3 channels
constexpr int P   = 262144;        // 512*512 pixels / channel
constexpr int NB  = 256;           // bins

// Pipeline structure — the validated-optimal R7 configuration (93.8us).
constexpr int GROUPS = 8;
constexpr int CPG    = NCH / GROUPS;   // 24 channels per group
constexpr int HPC    = 8;              // hist blocks per channel
constexpr int APC    = 16;             // apply blocks per channel
constexpr int NHIST  = CPG * HPC;      // 192 hist-role blocks
constexpr int NAPPLY = CPG * APC;      // 384 apply-role blocks
constexpr int NBLK   = NHIST + NAPPLY; // 576 <= 148*4 -> single co-resident wave

// Scratch — __device__ globals (zero at load; cleanup kernel re-zeroes per replay)
__device__ int g_hist[NCH * NB];
__device__ int g_ctr [GROUPS];

// ---------------------------------------------------------------------------
// Fused persistent kernel: role-specialized producer/consumer pipeline.
// hist blocks (read-bound) and apply blocks (write-bound) co-run, overlapping
// DRAM read and write streams that a two-pass structure serializes.
// 603MB total traffic at ~6.7TB/s effective = the measured DRAM ceiling.
// ---------------------------------------------------------------------------
__global__ void __launch_bounds__(256, 4) fused_kernel(const float* __restrict__ in,
                                                       float* __restrict__ out) {
    __shared__ int sh[8 * NB];     // hist: 8 per-warp hists. apply: H/CS/RED/LUT.
    const int tid = threadIdx.x;
    const int bid = blockIdx.x;

    if (bid < NHIST) {
        // ---------------- HIST ROLE ----------------
        const int cg = bid / HPC;          // channel within group
        const int h  = bid % HPC;          // slice within channel
        int* const myh = &sh[(tid >> 5) * NB];

        for (int g = 0; g < GROUPS; g++) {
            const int c = g * CPG + cg;
            for (int i = tid; i < 8 * NB; i += 256) sh[i] = 0;
            __syncthreads();

            const float4* bi =
                reinterpret_cast<const float4*>(in + (size_t)c * P) + h * (P / 4 / HPC);
            for (int i = tid; i < P / 4 / HPC; i += 512) {   // 8192 float4 / slice
                float4 a = bi[i];
                float4 b = bi[i + 256];
                atomicAdd(&myh[(int)a.x], 1);
                atomicAdd(&myh[(int)a.y], 1);
                atomicAdd(&myh[(int)a.z], 1);
                atomicAdd(&myh[(int)a.w], 1);
                atomicAdd(&myh[(int)b.x], 1);
                atomicAdd(&myh[(int)b.y], 1);
                atomicAdd(&myh[(int)b.z], 1);
                atomicAdd(&myh[(int)b.w], 1);
            }
            __syncthreads();

            // Reduce 8 warp-hists -> global
            int s = 0;
#pragma unroll
            for (int k = 0; k < 8; k++) s += sh[k * NB + tid];
            if (s) atomicAdd(&g_hist[c * NB + tid], s);

            __threadfence();               // release my hist contributions
            __syncthreads();               // all threads' atomics+fences done
            if (tid == 0) atomicAdd(&g_ctr[g], 1);
        }
    } else {
        // ---------------- APPLY ROLE ----------------
        const int a  = bid - NHIST;
        const int cg = a / APC;            // channel within group
        const int j  = a % APC;            // slice within channel
        int*   H   = sh;
        int*   CS  = sh + NB;
        int*   RED = sh + 2 * NB;
        float* LUT = reinterpret_cast<float*>(sh + 3 * NB);

        for (int g = 0; g < GROUPS; g++) {
            const int c = g * CPG + cg;

            // Wait until all hist blocks of this group have published.
            if (tid == 0) {
                while (*(volatile int*)&g_ctr[g] < NHIST) __nanosleep(128);
            }
            __syncthreads();
            __threadfence();

            // Build this channel's LUT locally (exact PIL integer math).
            const int hv = __ldcg(&g_hist[c * NB + tid]);
            H[tid]  = hv;
            CS[tid] = hv;
            __syncthreads();
#pragma unroll
            for (int off = 1; off < NB; off <<= 1) {       // inclusive scan
                int v = (tid >= off) ? CS[tid - off] : 0;
                __syncthreads();
                CS[tid] += v;
                __syncthreads();
            }
            RED[tid] = hv ? tid : -1;                      // last nonzero bin
            __syncthreads();
#pragma unroll
            for (int sdx = 128; sdx > 0; sdx >>= 1) {
                if (tid < sdx) RED[tid] = max(RED[tid], RED[tid + sdx]);
                __syncthreads();
            }
            const int last_val = H[RED[0]];
            const int step = (P - last_val) / 255;
            const int safe = step > 0 ? step : 1;
            const int prev = tid ? CS[tid - 1] : 0;
            int lv = (prev + step / 2) / safe;
            lv = min(max(lv, 0), 255);
            if (step == 0) lv = tid;       // passthrough as identity LUT
            LUT[tid] = (float)lv;
            __syncthreads();

            // Apply this block's slice: 4096 float4, 2 loads in flight.
            const float4* bi =
                reinterpret_cast<const float4*>(in + (size_t)c * P) + j * (P / 4 / APC);
            float4* bo =
                reinterpret_cast<float4*>(out + (size_t)c * P) + j * (P / 4 / APC);
            for (int i = tid; i < P / 4 / APC; i += 512) {
                float4 x = bi[i];
                float4 y = bi[i + 256];
                float4 ox, oy;
                ox.x = LUT[(int)x.x]; ox.y = LUT[(int)x.y];
                ox.z = LUT[(int)x.z]; ox.w = LUT[(int)x.w];
                oy.x = LUT[(int)y.x]; oy.y = LUT[(int)y.y];
                oy.z = LUT[(int)y.z]; oy.w = LUT[(int)y.w];
                __stcs(&bo[i], ox);            // evict-first writes: protect L2
                __stcs(&bo[i + 256], oy);      // residency of upcoming input
            }
            __syncthreads();                    // smem reuse next group
        }
    }
}

// ---------------------------------------------------------------------------
// Cleanup: restore pristine scratch state so the next graph replay is clean.
// ---------------------------------------------------------------------------
__global__ void cleanup_kernel() {
    g_hist[blockIdx.x * NB + threadIdx.x] = 0;
    if (blockIdx.x == 0 && threadIdx.x < GROUPS) g_ctr[threadIdx.x] = 0;
}

// ---------------------------------------------------------------------------
extern "C" void kernel_launch(void* const* d_in, const int* in_sizes, int n_in,
                              void* d_out, int out_size) {
    const float* img = (const float*)d_in[0];
    float* out = (float*)d_out;

    fused_kernel<<<NBLK, 256>>>(img, out);
    cleanup_kernel<<<NCH, NB>>>();
}